// round 2
// baseline (speedup 1.0000x reference)
#include <cuda_runtime.h>
#include <math.h>

// Problem dims
#define NT 4096      // tokens
#define NDM 2048     // d_model
#define NF 8192      // d_ff
#define NE 8         // experts

// Tiling
#define BM 128
#define BN 128
#define BK 16

// -------- device scratch (no allocations allowed) --------
__device__ int   g_counts[NE];
__device__ int   g_tok[NE][NT];
__device__ float g_w[NT];
__device__ float g_h[(size_t)NT * NF];   // 128 MB hidden activations

__device__ __forceinline__ float gelu_exact(float v) {
    return 0.5f * v * (1.0f + erff(v * 0.70710678118654752440f));
}

__global__ void reset_kernel() {
    if (threadIdx.x < NE) g_counts[threadIdx.x] = 0;
}

// One block (256 threads) per token: logits over 8 experts, softmax max prob,
// argmax expert, atomic append into that expert's bucket.
__global__ void router_kernel(const float* __restrict__ x,
                              const float* __restrict__ Wr) {
    const int t = blockIdx.x;
    const float* xr = x + (size_t)t * NDM;
    float acc[NE];
#pragma unroll
    for (int e = 0; e < NE; e++) acc[e] = 0.f;
    for (int d = threadIdx.x; d < NDM; d += 256) {
        const float xv = xr[d];
#pragma unroll
        for (int e = 0; e < NE; e++) acc[e] += xv * Wr[e * NDM + d];
    }
#pragma unroll
    for (int off = 16; off > 0; off >>= 1) {
#pragma unroll
        for (int e = 0; e < NE; e++)
            acc[e] += __shfl_down_sync(0xffffffffu, acc[e], off);
    }
    __shared__ float red[8][NE];
    const int warp = threadIdx.x >> 5;
    const int lane = threadIdx.x & 31;
    if (lane == 0) {
#pragma unroll
        for (int e = 0; e < NE; e++) red[warp][e] = acc[e];
    }
    __syncthreads();
    if (threadIdx.x == 0) {
        float l[NE];
#pragma unroll
        for (int e = 0; e < NE; e++) {
            float s = 0.f;
#pragma unroll
            for (int w = 0; w < 8; w++) s += red[w][e];
            l[e] = s;
        }
        float m = l[0]; int bi = 0;
#pragma unroll
        for (int e = 1; e < NE; e++) {
            if (l[e] > m) { m = l[e]; bi = e; }   // strict '>' keeps first max (jnp.argmax)
        }
        float s = 0.f;
#pragma unroll
        for (int e = 0; e < NE; e++) s += expf(l[e] - m);
        g_w[t] = 1.0f / s;                        // max softmax prob
        const int slot = atomicAdd(&g_counts[bi], 1);
        g_tok[bi][slot] = t;
    }
}

// Grouped-gather SGEMM. FFN1: H[t,:] = gelu(x[t,:] @ W1[e])  (K=NDM, N=NF)
//                      FFN2: out[t,:] = (H[t,:] @ W2[e]) * w[t] (K=NF, N=NDM)
// Block = 128x128 tile of (expert-local tokens) x (output cols), BK=16, 256 thr,
// 8x8 micro-tile per thread.
template <bool FFN1>
__global__ __launch_bounds__(256, 2)
void moe_gemm(const float* __restrict__ Ain,
              const float* __restrict__ Bw,
              float* __restrict__ Cout) {
    constexpr int KD = FFN1 ? NDM : NF;
    constexpr int NDIM = FFN1 ? NF : NDM;

    const int e   = blockIdx.z;
    const int cnt = g_counts[e];
    const int m0  = blockIdx.y * BM;
    if (m0 >= cnt) return;
    const int n0  = blockIdx.x * BN;

    const float* __restrict__ A = FFN1 ? Ain : (const float*)g_h;

    __shared__ float As[BK][BM];
    __shared__ float Bs[BK][BN];
    __shared__ int   toks[BM];

    const int tid = threadIdx.x;
    if (tid < BM) {
        const int m = m0 + tid;
        toks[tid] = (m < cnt) ? g_tok[e][m] : -1;
    }
    __syncthreads();

    // A load: 128 rows x 16 k; 2 threads/row, 8 consecutive k each (2x float4)
    const int arow = tid >> 1;
    const int akq  = (tid & 1) * 8;
    const int atok = toks[arow];
    const float* aptr = (atok >= 0) ? (A + (size_t)atok * KD + akq) : A;

    // B load: 16 k-rows x 128 cols; 16 threads/row, 8 consecutive cols (2x float4)
    const int bk = tid >> 4;
    const int bn = (tid & 15) * 8;
    const float* bptr = Bw + (size_t)e * KD * NDIM + (size_t)bk * NDIM + (n0 + bn);

    const int ty = tid >> 4;   // row group 0..15 -> rows ty*8..ty*8+7
    const int tx = tid & 15;   // col group 0..15 -> cols tx*8..tx*8+7

    float acc[8][8];
#pragma unroll
    for (int i = 0; i < 8; i++)
#pragma unroll
        for (int j = 0; j < 8; j++) acc[i][j] = 0.f;

    for (int kb = 0; kb < KD; kb += BK) {
        float4 a0 = make_float4(0.f, 0.f, 0.f, 0.f), a1 = a0;
        if (atok >= 0) {
            a0 = *(const float4*)(aptr + kb);
            a1 = *(const float4*)(aptr + kb + 4);
        }
        const float4 b0 = *(const float4*)(bptr + (size_t)kb * NDIM);
        const float4 b1 = *(const float4*)(bptr + (size_t)kb * NDIM + 4);

        As[akq + 0][arow] = a0.x; As[akq + 1][arow] = a0.y;
        As[akq + 2][arow] = a0.z; As[akq + 3][arow] = a0.w;
        As[akq + 4][arow] = a1.x; As[akq + 5][arow] = a1.y;
        As[akq + 6][arow] = a1.z; As[akq + 7][arow] = a1.w;
        *(float4*)&Bs[bk][bn]     = b0;
        *(float4*)&Bs[bk][bn + 4] = b1;
        __syncthreads();

#pragma unroll
        for (int k = 0; k < BK; k++) {
            float a[8], b[8];
            *(float4*)(a)     = *(const float4*)&As[k][ty * 8];
            *(float4*)(a + 4) = *(const float4*)&As[k][ty * 8 + 4];
            *(float4*)(b)     = *(const float4*)&Bs[k][tx * 8];
            *(float4*)(b + 4) = *(const float4*)&Bs[k][tx * 8 + 4];
#pragma unroll
            for (int i = 0; i < 8; i++)
#pragma unroll
                for (int j = 0; j < 8; j++)
                    acc[i][j] += a[i] * b[j];
        }
        __syncthreads();
    }

    // Epilogue
#pragma unroll
    for (int i = 0; i < 8; i++) {
        const int tk = toks[ty * 8 + i];
        if (tk < 0) continue;
        if (FFN1) {
            float* o = g_h + (size_t)tk * NF + (n0 + tx * 8);
            float4 v0, v1;
            v0.x = gelu_exact(acc[i][0]); v0.y = gelu_exact(acc[i][1]);
            v0.z = gelu_exact(acc[i][2]); v0.w = gelu_exact(acc[i][3]);
            v1.x = gelu_exact(acc[i][4]); v1.y = gelu_exact(acc[i][5]);
            v1.z = gelu_exact(acc[i][6]); v1.w = gelu_exact(acc[i][7]);
            *(float4*)o = v0; *(float4*)(o + 4) = v1;
        } else {
            const float w = g_w[tk];
            float* o = Cout + (size_t)tk * NDM + (n0 + tx * 8);
            float4 v0, v1;
            v0.x = acc[i][0] * w; v0.y = acc[i][1] * w;
            v0.z = acc[i][2] * w; v0.w = acc[i][3] * w;
            v1.x = acc[i][4] * w; v1.y = acc[i][5] * w;
            v1.z = acc[i][6] * w; v1.w = acc[i][7] * w;
            *(float4*)o = v0; *(float4*)(o + 4) = v1;
        }
    }
}

extern "C" void kernel_launch(void* const* d_in, const int* in_sizes, int n_in,
                              void* d_out, int out_size) {
    (void)in_sizes; (void)n_in; (void)out_size;
    const float* x  = (const float*)d_in[0];
    const float* Wr = (const float*)d_in[1];
    const float* W1 = (const float*)d_in[2];
    const float* W2 = (const float*)d_in[3];
    float* out = (float*)d_out;

    reset_kernel<<<1, 32>>>();
    router_kernel<<<NT, 256>>>(x, Wr);

    dim3 g1(NF / BN, NT / BM, NE);   // (64, 32, 8); blocks past each expert's count exit early
    moe_gemm<true><<<g1, 256>>>(x, W1, out);

    dim3 g2(NDM / BN, NT / BM, NE);  // (16, 32, 8)
    moe_gemm<false><<<g2, 256>>>(x, W2, out);
}

// round 6
// speedup vs baseline: 2.2967x; 2.2967x over previous
#include <cuda_runtime.h>
#include <math.h>
#include <stdint.h>

#define NT 4096      // tokens
#define NDM 2048     // d_model
#define NF 8192      // d_ff
#define NE 8         // experts

#define BM 128
#define BN 128
#define BK 32
#define STAGES 3

#define AS_STRIDE 36   // BK + 4 floats pad
#define BS_STRIDE 132  // BN + 4 floats pad
#define A_STAGE (BM * AS_STRIDE)   // floats
#define B_STAGE (BK * BS_STRIDE)   // floats
#define SMEM_FLOATS (STAGES * (A_STAGE + B_STAGE))
#define SMEM_BYTES (SMEM_FLOATS * 4 + 512)

// -------- device scratch --------
__device__ int   g_counts[NE];
__device__ int   g_tok[NE][NT];
__device__ float g_w[NT];
__device__ float g_h[(size_t)NT * NF];

__device__ __forceinline__ float gelu_exact(float v) {
    return 0.5f * v * (1.0f + erff(v * 0.70710678118654752440f));
}

__global__ void reset_kernel() {
    if (threadIdx.x < NE) g_counts[threadIdx.x] = 0;
}

__global__ void router_kernel(const float* __restrict__ x,
                              const float* __restrict__ Wr) {
    const int t = blockIdx.x;
    const float* xr = x + (size_t)t * NDM;
    float acc[NE];
#pragma unroll
    for (int e = 0; e < NE; e++) acc[e] = 0.f;
    for (int d = threadIdx.x; d < NDM; d += 256) {
        const float xv = xr[d];
#pragma unroll
        for (int e = 0; e < NE; e++) acc[e] += xv * Wr[e * NDM + d];
    }
#pragma unroll
    for (int off = 16; off > 0; off >>= 1) {
#pragma unroll
        for (int e = 0; e < NE; e++)
            acc[e] += __shfl_down_sync(0xffffffffu, acc[e], off);
    }
    __shared__ float red[8][NE];
    const int warp = threadIdx.x >> 5;
    const int lane = threadIdx.x & 31;
    if (lane == 0) {
#pragma unroll
        for (int e = 0; e < NE; e++) red[warp][e] = acc[e];
    }
    __syncthreads();
    if (threadIdx.x == 0) {
        float l[NE];
#pragma unroll
        for (int e = 0; e < NE; e++) {
            float s = 0.f;
#pragma unroll
            for (int w = 0; w < 8; w++) s += red[w][e];
            l[e] = s;
        }
        float m = l[0]; int bi = 0;
#pragma unroll
        for (int e = 1; e < NE; e++) {
            if (l[e] > m) { m = l[e]; bi = e; }  // first-max = jnp.argmax
        }
        float s = 0.f;
#pragma unroll
        for (int e = 0; e < NE; e++) s += expf(l[e] - m);
        g_w[t] = 1.0f / s;
        const int slot = atomicAdd(&g_counts[bi], 1);
        g_tok[bi][slot] = t;
    }
}

// -------- cp.async helpers --------
static __device__ __forceinline__ void cp_async16(uint32_t dst, const void* src, int src_bytes) {
    asm volatile("cp.async.cg.shared.global [%0], [%1], 16, %2;"
                 :: "r"(dst), "l"(src), "r"(src_bytes));
}
static __device__ __forceinline__ void cp_commit() {
    asm volatile("cp.async.commit_group;" ::: "memory");
}
static __device__ __forceinline__ void cp_wait1() {
    asm volatile("cp.async.wait_group 1;" ::: "memory");
}

// Round-to-nearest fp32 -> tf32 (kills the coherent truncation bias of raw HMMA feed)
static __device__ __forceinline__ uint32_t f2tf32(float f) {
    uint32_t u; asm("cvt.rna.tf32.f32 %0, %1;" : "=r"(u) : "f"(f)); return u;
}

static __device__ __forceinline__ void mma_tf32(float* c, const uint32_t* a, const uint32_t* b) {
    asm volatile(
        "mma.sync.aligned.m16n8k8.row.col.f32.tf32.tf32.f32 "
        "{%0,%1,%2,%3}, {%4,%5,%6,%7}, {%8,%9}, {%0,%1,%2,%3};"
        : "+f"(c[0]), "+f"(c[1]), "+f"(c[2]), "+f"(c[3])
        : "r"(a[0]), "r"(a[1]), "r"(a[2]), "r"(a[3]), "r"(b[0]), "r"(b[1]));
}

// -------- grouped TF32 mma.sync GEMM --------
template <bool F1>
__global__ __launch_bounds__(256, 2)
void moe_mma(const float* __restrict__ Asrc,
             const float* __restrict__ W,
             float* __restrict__ Out) {
    constexpr int KD = F1 ? NDM : NF;
    constexpr int ND = F1 ? NF : NDM;
    constexpr int NK = KD / BK;

    const int e   = blockIdx.z;
    const int cnt = g_counts[e];
    const int m0  = blockIdx.y * BM;
    if (m0 >= cnt) return;
    const int n0  = blockIdx.x * BN;

    extern __shared__ float smem[];
    float* As = smem;                      // [STAGES][BM][AS_STRIDE]
    float* Bs = smem + STAGES * A_STAGE;   // [STAGES][BK][BS_STRIDE]
    int* toks = (int*)(Bs + STAGES * B_STAGE);

    const int tid  = threadIdx.x;
    const int wid  = tid >> 5;
    const int lane = tid & 31;

    if (tid < BM) {
        const int m = m0 + tid;
        toks[tid] = (m < cnt) ? g_tok[e][m] : -1;
    }
    __syncthreads();

    const float* A = F1 ? Asrc : (const float*)g_h;

    // A loads: 2 threads/row, 16 consecutive floats each (4x cp.async16)
    const int arow = tid >> 1;
    const int afo  = (tid & 1) * 16;
    const int atok = toks[arow];
    const int apred = (atok >= 0) ? 16 : 0;
    const float* a_src = A + (atok >= 0 ? (size_t)atok * KD : 0) + afo;
    const uint32_t a_dst = (uint32_t)__cvta_generic_to_shared(As + arow * AS_STRIDE + afo);

    // B loads: 8 threads/k-row, 16 consecutive floats each
    const int bk  = tid >> 3;
    const int bfo = (tid & 7) * 16;
    const float* b_src = W + (size_t)e * KD * ND + (size_t)bk * ND + (n0 + bfo);
    const uint32_t b_dst = (uint32_t)__cvta_generic_to_shared(Bs + bk * BS_STRIDE + bfo);

    auto issue = [&](int t) {
        if (t < NK) {
            const int s = t % STAGES;
            const uint32_t ad = a_dst + s * (A_STAGE * 4);
            const float* ag = a_src + t * BK;
#pragma unroll
            for (int i = 0; i < 4; i++)
                cp_async16(ad + i * 16, ag + i * 4, apred);
            const uint32_t bd = b_dst + s * (B_STAGE * 4);
            const float* bg = b_src + (size_t)t * BK * ND;
#pragma unroll
            for (int i = 0; i < 4; i++)
                cp_async16(bd + i * 16, bg + i * 4, 16);
        }
        cp_commit();
    };

    issue(0);
    issue(1);

    const int wm0 = (wid & 3) * 32;   // warp M origin (2 mtiles of 16)
    const int wn0 = (wid >> 2) * 64;  // warp N origin (8 ntiles of 8)
    const int qr = lane >> 2;         // 0..7
    const int qc = lane & 3;          // 0..3

    float acc[2][8][4];
#pragma unroll
    for (int mt = 0; mt < 2; mt++)
#pragma unroll
        for (int nt = 0; nt < 8; nt++)
#pragma unroll
            for (int i = 0; i < 4; i++) acc[mt][nt][i] = 0.f;

#pragma unroll 1
    for (int t = 0; t < NK; t++) {
        cp_wait1();
        __syncthreads();
        issue(t + 2);

        const float* As_s = As + (t % STAGES) * A_STAGE;
        const float* Bs_s = Bs + (t % STAGES) * B_STAGE;

#pragma unroll
        for (int ks = 0; ks < 4; ks++) {
            const int kc = ks * 8 + qc;
            uint32_t af[2][4];
#pragma unroll
            for (int mt = 0; mt < 2; mt++) {
                const int r = wm0 + mt * 16 + qr;
                af[mt][0] = f2tf32(As_s[r * AS_STRIDE + kc]);
                af[mt][1] = f2tf32(As_s[(r + 8) * AS_STRIDE + kc]);
                af[mt][2] = f2tf32(As_s[r * AS_STRIDE + kc + 4]);
                af[mt][3] = f2tf32(As_s[(r + 8) * AS_STRIDE + kc + 4]);
            }
#pragma unroll
            for (int nh = 0; nh < 2; nh++) {
                uint32_t bf[4][2];
#pragma unroll
                for (int j = 0; j < 4; j++) {
                    const int nn = wn0 + (nh * 4 + j) * 8 + qr;
                    bf[j][0] = f2tf32(Bs_s[kc * BS_STRIDE + nn]);
                    bf[j][1] = f2tf32(Bs_s[(kc + 4) * BS_STRIDE + nn]);
                }
#pragma unroll
                for (int mt = 0; mt < 2; mt++)
#pragma unroll
                    for (int j = 0; j < 4; j++)
                        mma_tf32(acc[mt][nh * 4 + j], af[mt], bf[j]);
            }
        }
    }

    // Epilogue: c0:(r,2c) c1:(r,2c+1) c2:(r+8,2c) c3:(r+8,2c+1)
#pragma unroll
    for (int mt = 0; mt < 2; mt++) {
        const int rb0 = wm0 + mt * 16 + qr;
        const int tok0 = toks[rb0];
        const int tok1 = toks[rb0 + 8];
#pragma unroll
        for (int nt = 0; nt < 8; nt++) {
            const int col = n0 + wn0 + nt * 8 + qc * 2;
            if (F1) {
                if (tok0 >= 0) {
                    float2 v = make_float2(gelu_exact(acc[mt][nt][0]),
                                           gelu_exact(acc[mt][nt][1]));
                    *(float2*)(g_h + (size_t)tok0 * NF + col) = v;
                }
                if (tok1 >= 0) {
                    float2 v = make_float2(gelu_exact(acc[mt][nt][2]),
                                           gelu_exact(acc[mt][nt][3]));
                    *(float2*)(g_h + (size_t)tok1 * NF + col) = v;
                }
            } else {
                if (tok0 >= 0) {
                    const float w0 = g_w[tok0];
                    float2 v = make_float2(acc[mt][nt][0] * w0, acc[mt][nt][1] * w0);
                    *(float2*)(Out + (size_t)tok0 * NDM + col) = v;
                }
                if (tok1 >= 0) {
                    const float w1 = g_w[tok1];
                    float2 v = make_float2(acc[mt][nt][2] * w1, acc[mt][nt][3] * w1);
                    *(float2*)(Out + (size_t)tok1 * NDM + col) = v;
                }
            }
        }
    }
}

extern "C" void kernel_launch(void* const* d_in, const int* in_sizes, int n_in,
                              void* d_out, int out_size) {
    (void)in_sizes; (void)n_in; (void)out_size;
    const float* x  = (const float*)d_in[0];
    const float* Wr = (const float*)d_in[1];
    const float* W1 = (const float*)d_in[2];
    const float* W2 = (const float*)d_in[3];
    float* out = (float*)d_out;

    cudaFuncSetAttribute(moe_mma<true>,  cudaFuncAttributeMaxDynamicSharedMemorySize, SMEM_BYTES);
    cudaFuncSetAttribute(moe_mma<false>, cudaFuncAttributeMaxDynamicSharedMemorySize, SMEM_BYTES);

    reset_kernel<<<1, 32>>>();
    router_kernel<<<NT, 256>>>(x, Wr);

    dim3 g1(NF / BN, NT / BM, NE);    // (64, 32, 8)
    moe_mma<true><<<g1, 256, SMEM_BYTES>>>(x, W1, out);

    dim3 g2(NDM / BN, NT / BM, NE);   // (16, 32, 8)
    moe_mma<false><<<g2, 256, SMEM_BYTES>>>(x, W2, out);
}

// round 9
// speedup vs baseline: 3.0481x; 1.3271x over previous
#include <cuda_runtime.h>
#include <math.h>
#include <stdint.h>

#define NT 4096      // tokens
#define NDM 2048     // d_model
#define NF 8192      // d_ff
#define NE 8         // experts

#define BM 128
#define BN 128
#define BK 32

// 16B fragment words; tiles of 32 words padded for bank-conflict-free STS
#define A_TILE_W 33                      // 16x8 A mtile: 32 words + 1 pad
#define B_TILE_W 36                      // 8x16 B npair-tile: 32 words + 4 pad
#define A_STAGE_B (32 * A_TILE_W * 16)   // 16896 B
#define B_STAGE_B (32 * B_TILE_W * 16)   // 18432 B
#define STAGE_B   (A_STAGE_B + B_STAGE_B) // 35328 B
#define SMEM_BYTES (2 * STAGE_B + 640)

// -------- device scratch --------
__device__ int   g_counts[NE];
__device__ int   g_tok[NE][NT];
__device__ float g_w[NT];
__device__ float g_h[(size_t)NT * NF];

__device__ __forceinline__ float gelu_exact(float v) {
    return 0.5f * v * (1.0f + erff(v * 0.70710678118654752440f));
}

__global__ void reset_kernel() {
    if (threadIdx.x < NE) g_counts[threadIdx.x] = 0;
}

__global__ void router_kernel(const float* __restrict__ x,
                              const float* __restrict__ Wr) {
    const int t = blockIdx.x;
    const float* xr = x + (size_t)t * NDM;
    float acc[NE];
#pragma unroll
    for (int e = 0; e < NE; e++) acc[e] = 0.f;
    for (int d = threadIdx.x; d < NDM; d += 256) {
        const float xv = xr[d];
#pragma unroll
        for (int e = 0; e < NE; e++) acc[e] += xv * Wr[e * NDM + d];
    }
#pragma unroll
    for (int off = 16; off > 0; off >>= 1) {
#pragma unroll
        for (int e = 0; e < NE; e++)
            acc[e] += __shfl_down_sync(0xffffffffu, acc[e], off);
    }
    __shared__ float red[8][NE];
    const int warp = threadIdx.x >> 5;
    const int lane = threadIdx.x & 31;
    if (lane == 0) {
#pragma unroll
        for (int e = 0; e < NE; e++) red[warp][e] = acc[e];
    }
    __syncthreads();
    if (threadIdx.x == 0) {
        float l[NE];
#pragma unroll
        for (int e = 0; e < NE; e++) {
            float s = 0.f;
#pragma unroll
            for (int w = 0; w < 8; w++) s += red[w][e];
            l[e] = s;
        }
        float m = l[0]; int bi = 0;
#pragma unroll
        for (int e = 1; e < NE; e++) {
            if (l[e] > m) { m = l[e]; bi = e; }  // first-max = jnp.argmax
        }
        float s = 0.f;
#pragma unroll
        for (int e = 0; e < NE; e++) s += expf(l[e] - m);
        g_w[t] = 1.0f / s;
        const int slot = atomicAdd(&g_counts[bi], 1);
        g_tok[bi][slot] = t;
    }
}

// -------- asm helpers --------
static __device__ __forceinline__ uint32_t f2tf32(float f) {
    uint32_t u; asm("cvt.rna.tf32.f32 %0, %1;" : "=r"(u) : "f"(f)); return u;
}
static __device__ __forceinline__ void sts128(uint32_t a, uint32_t x, uint32_t y,
                                              uint32_t z, uint32_t w) {
    asm volatile("st.shared.v4.b32 [%0], {%1,%2,%3,%4};"
                 :: "r"(a), "r"(x), "r"(y), "r"(z), "r"(w));
}
static __device__ __forceinline__ void lds128(uint32_t a, uint32_t* r) {
    asm volatile("ld.shared.v4.b32 {%0,%1,%2,%3}, [%4];"
                 : "=r"(r[0]), "=r"(r[1]), "=r"(r[2]), "=r"(r[3]) : "r"(a));
}
static __device__ __forceinline__ void mma_tf32(float* c, const uint32_t* a, const uint32_t* b) {
    asm volatile(
        "mma.sync.aligned.m16n8k8.row.col.f32.tf32.tf32.f32 "
        "{%0,%1,%2,%3}, {%4,%5,%6,%7}, {%8,%9}, {%0,%1,%2,%3};"
        : "+f"(c[0]), "+f"(c[1]), "+f"(c[2]), "+f"(c[3])
        : "r"(a[0]), "r"(a[1]), "r"(a[2]), "r"(a[3]), "r"(b[0]), "r"(b[1]));
}

// -------- grouped TF32 GEMM, fragment-ordered smem --------
// A word (16B) @ tile(mrow,kseg), word(rlow*4+kc) = {(r,k),(r+8,k),(r,k+4),(r+8,k+4)}
// B word (16B) @ tile(kseg*8+npair), word(qr*4+qc) = {(k,n),(k+4,n),(k,n+8),(k+4,n+8)}
template <bool F1>
__global__ __launch_bounds__(256, 2)
void moe_mma(const float* __restrict__ Asrc,
             const float* __restrict__ W,
             float* __restrict__ Out) {
    constexpr int KD = F1 ? NDM : NF;
    constexpr int ND = F1 ? NF : NDM;
    constexpr int NK = KD / BK;

    const int e   = blockIdx.z;
    const int cnt = g_counts[e];
    const int m0  = blockIdx.y * BM;
    if (m0 >= cnt) return;
    const int n0  = blockIdx.x * BN;

    extern __shared__ float smem[];
    int* toks = (int*)((char*)smem + 2 * STAGE_B);
    const uint32_t sbase = (uint32_t)__cvta_generic_to_shared(smem);

    const int tid  = threadIdx.x;
    const int wid  = tid >> 5;
    const int lane = tid & 31;

    if (tid < BM) {
        const int m = m0 + tid;
        toks[tid] = (m < cnt) ? g_tok[e][m] : -1;
    }
    __syncthreads();

    const float* A = F1 ? Asrc : (const float*)g_h;

    // ---- A loader: thread -> rows (r, r+8), k-range kseg*8..+7
    const int a_ks   = tid & 3;
    const int a_rp   = tid >> 2;
    const int a_rlow = a_rp & 7;
    const int a_mrow = a_rp >> 3;          // == wid
    const int ar0 = a_mrow * 16 + a_rlow;
    const int atok0 = toks[ar0];
    const int atok1 = toks[ar0 + 8];
    const float* ap0 = A + (atok0 >= 0 ? (size_t)atok0 * KD : 0) + a_ks * 8;
    const float* ap1 = A + (atok1 >= 0 ? (size_t)atok1 * KD : 0) + a_ks * 8;
    const uint32_t a_sts = sbase +
        (uint32_t)(((a_mrow * 4 + a_ks) * A_TILE_W + a_rlow * 4) * 16);

    // ---- B loader: thread -> rows (klo, klo+4), cols nb..nb+3 & nb+8..nb+11
    const int b_kc  = tid & 3;
    const int b_npl = (tid >> 2) & 3;
    const int b_ns  = (tid >> 4) & 1;
    const int b_ksg = (tid >> 5) & 3;
    const int b_nph = (tid >> 7) & 1;
    const int b_np  = b_nph * 4 + b_npl;
    const int b_nb  = b_np * 16 + b_ns * 4;
    const int b_klo = b_ksg * 8 + b_kc;
    const float* bp = W + (size_t)e * KD * ND + (size_t)b_klo * ND + (n0 + b_nb);
    const uint32_t b_sts = sbase + A_STAGE_B +
        (uint32_t)(((b_ksg * 8 + b_np) * B_TILE_W + b_ns * 16 + b_kc) * 16);

    // ---- consumer bases
    const int wm = wid & 3;   // warp M quad (32 rows)
    const int wn = wid >> 2;  // warp N half (64 cols)
    const uint32_t aLds0 = sbase + (uint32_t)(wm * 8 * A_TILE_W * 16) + lane * 16;
    const uint32_t bLds0 = sbase + A_STAGE_B + (uint32_t)(wn * 4 * B_TILE_W * 16) + lane * 16;

    float4 fa0, fa1, fb0, fb1;   // A prefetch
    float4 g0, g1, g2, g3;       // B prefetch

#define LOAD(T)                                                            \
    {                                                                      \
        const float* _a0 = ap0 + (size_t)(T) * BK;                         \
        const float* _a1 = ap1 + (size_t)(T) * BK;                         \
        fa0 = *(const float4*)_a0; fa1 = *(const float4*)(_a0 + 4);        \
        fb0 = *(const float4*)_a1; fb1 = *(const float4*)(_a1 + 4);        \
        const float* _b = bp + (size_t)(T) * BK * ND;                      \
        g0 = *(const float4*)_b;                                           \
        g1 = *(const float4*)(_b + 8);                                     \
        g2 = *(const float4*)(_b + 4 * (size_t)ND);                        \
        g3 = *(const float4*)(_b + 4 * (size_t)ND + 8);                    \
    }

#define STORE(OFF)                                                         \
    {                                                                      \
        const uint32_t _as = a_sts + (OFF);                                \
        sts128(_as,      f2tf32(fa0.x), f2tf32(fb0.x), f2tf32(fa1.x), f2tf32(fb1.x)); \
        sts128(_as + 16, f2tf32(fa0.y), f2tf32(fb0.y), f2tf32(fa1.y), f2tf32(fb1.y)); \
        sts128(_as + 32, f2tf32(fa0.z), f2tf32(fb0.z), f2tf32(fa1.z), f2tf32(fb1.z)); \
        sts128(_as + 48, f2tf32(fa0.w), f2tf32(fb0.w), f2tf32(fa1.w), f2tf32(fb1.w)); \
        const uint32_t _bs = b_sts + (OFF);                                \
        sts128(_bs,       f2tf32(g0.x), f2tf32(g2.x), f2tf32(g1.x), f2tf32(g3.x)); \
        sts128(_bs + 64,  f2tf32(g0.y), f2tf32(g2.y), f2tf32(g1.y), f2tf32(g3.y)); \
        sts128(_bs + 128, f2tf32(g0.z), f2tf32(g2.z), f2tf32(g1.z), f2tf32(g3.z)); \
        sts128(_bs + 192, f2tf32(g0.w), f2tf32(g2.w), f2tf32(g1.w), f2tf32(g3.w)); \
    }

    float acc[2][4][2][4];
#pragma unroll
    for (int i = 0; i < 2; i++)
#pragma unroll
        for (int p = 0; p < 4; p++)
#pragma unroll
            for (int s = 0; s < 2; s++)
#pragma unroll
                for (int q = 0; q < 4; q++) acc[i][p][s][q] = 0.f;

#define MMASTEP(OFF)                                                       \
    {                                                                      \
        _Pragma("unroll") for (int ks = 0; ks < 4; ks++) {                 \
            uint32_t af0[4], af1[4], bf[4];                                \
            lds128(aLds0 + (OFF) + ks * (A_TILE_W * 16), af0);             \
            lds128(aLds0 + (OFF) + (ks + 4) * (A_TILE_W * 16), af1);       \
            _Pragma("unroll") for (int p = 0; p < 4; p++) {                \
                lds128(bLds0 + (OFF) + (ks * 8 + p) * (B_TILE_W * 16), bf);\
                mma_tf32(acc[0][p][0], af0, bf);                           \
                mma_tf32(acc[0][p][1], af0, bf + 2);                       \
                mma_tf32(acc[1][p][0], af1, bf);                           \
                mma_tf32(acc[1][p][1], af1, bf + 2);                       \
            }                                                              \
        }                                                                  \
    }

    LOAD(0)
    STORE(0)
    __syncthreads();

#pragma unroll 1
    for (int t = 0; t < NK; t++) {
        const bool more = (t + 1 < NK);
        if (more) LOAD(t + 1)
        MMASTEP((uint32_t)((t & 1) * STAGE_B))
        __syncthreads();
        if (more) {
            STORE((uint32_t)(((t + 1) & 1) * STAGE_B))
            __syncthreads();
        }
    }

    // ---- epilogue
    const int qr = lane >> 2;
    const int qc = lane & 3;
#pragma unroll
    for (int mt = 0; mt < 2; mt++) {
        const int r0 = wm * 32 + mt * 16 + qr;
        const int tok0 = toks[r0];
        const int tok1 = toks[r0 + 8];
#pragma unroll
        for (int p = 0; p < 4; p++)
#pragma unroll
            for (int sub = 0; sub < 2; sub++) {
                const int col = n0 + wn * 64 + p * 16 + sub * 8 + qc * 2;
                const float* c = acc[mt][p][sub];
                if (F1) {
                    if (tok0 >= 0) {
                        float2 v = make_float2(gelu_exact(c[0]), gelu_exact(c[1]));
                        *(float2*)(g_h + (size_t)tok0 * NF + col) = v;
                    }
                    if (tok1 >= 0) {
                        float2 v = make_float2(gelu_exact(c[2]), gelu_exact(c[3]));
                        *(float2*)(g_h + (size_t)tok1 * NF + col) = v;
                    }
                } else {
                    if (tok0 >= 0) {
                        const float w0 = g_w[tok0];
                        float2 v = make_float2(c[0] * w0, c[1] * w0);
                        *(float2*)(Out + (size_t)tok0 * NDM + col) = v;
                    }
                    if (tok1 >= 0) {
                        const float w1 = g_w[tok1];
                        float2 v = make_float2(c[2] * w1, c[3] * w1);
                        *(float2*)(Out + (size_t)tok1 * NDM + col) = v;
                    }
                }
            }
    }
#undef LOAD
#undef STORE
#undef MMASTEP
}

extern "C" void kernel_launch(void* const* d_in, const int* in_sizes, int n_in,
                              void* d_out, int out_size) {
    (void)in_sizes; (void)n_in; (void)out_size;
    const float* x  = (const float*)d_in[0];
    const float* Wr = (const float*)d_in[1];
    const float* W1 = (const float*)d_in[2];
    const float* W2 = (const float*)d_in[3];
    float* out = (float*)d_out;

    cudaFuncSetAttribute(moe_mma<true>,  cudaFuncAttributeMaxDynamicSharedMemorySize, SMEM_BYTES);
    cudaFuncSetAttribute(moe_mma<false>, cudaFuncAttributeMaxDynamicSharedMemorySize, SMEM_BYTES);

    reset_kernel<<<1, 32>>>();
    router_kernel<<<NT, 256>>>(x, Wr);

    dim3 g1(NF / BN, NT / BM, NE);    // (64, 32, 8)
    moe_mma<true><<<g1, 256, SMEM_BYTES>>>(x, W1, out);

    dim3 g2(NDM / BN, NT / BM, NE);   // (16, 32, 8)
    moe_mma<false><<<g2, 256, SMEM_BYTES>>>(x, W2, out);
}

// round 10
// speedup vs baseline: 3.7833x; 1.2412x over previous
#include <cuda_runtime.h>
#include <math.h>
#include <stdint.h>

#define NT 4096      // tokens
#define NDM 2048     // d_model
#define NF 8192      // d_ff
#define NE 8         // experts

#define BM 128
#define BN 256
#define BK 32

// 16B fragment words; tiles of 32 words padded for bank-conflict-free STS
#define A_TILE_W 33                       // 16x8 A mtile: 32 words + 1 pad
#define B_TILE_W 36                       // 8x16 B npair-tile: 32 words + 4 pad
#define A_STAGE_B (32 * A_TILE_W * 16)    // 16896 B
#define B_STAGE_B (64 * B_TILE_W * 16)    // 36864 B
#define STAGE_B   (A_STAGE_B + B_STAGE_B) // 53760 B
#define SMEM_BYTES (2 * STAGE_B + 640)    // ~105.6 KB

// -------- device scratch --------
__device__ int   g_counts[NE];
__device__ int   g_tok[NE][NT];
__device__ float g_w[NT];
__device__ float g_h[(size_t)NT * NF];

__device__ __forceinline__ float gelu_exact(float v) {
    return 0.5f * v * (1.0f + erff(v * 0.70710678118654752440f));
}

__global__ void reset_kernel() {
    if (threadIdx.x < NE) g_counts[threadIdx.x] = 0;
}

__global__ void router_kernel(const float* __restrict__ x,
                              const float* __restrict__ Wr) {
    const int t = blockIdx.x;
    const float* xr = x + (size_t)t * NDM;
    float acc[NE];
#pragma unroll
    for (int e = 0; e < NE; e++) acc[e] = 0.f;
    for (int d = threadIdx.x; d < NDM; d += 256) {
        const float xv = xr[d];
#pragma unroll
        for (int e = 0; e < NE; e++) acc[e] += xv * Wr[e * NDM + d];
    }
#pragma unroll
    for (int off = 16; off > 0; off >>= 1) {
#pragma unroll
        for (int e = 0; e < NE; e++)
            acc[e] += __shfl_down_sync(0xffffffffu, acc[e], off);
    }
    __shared__ float red[8][NE];
    const int warp = threadIdx.x >> 5;
    const int lane = threadIdx.x & 31;
    if (lane == 0) {
#pragma unroll
        for (int e = 0; e < NE; e++) red[warp][e] = acc[e];
    }
    __syncthreads();
    if (threadIdx.x == 0) {
        float l[NE];
#pragma unroll
        for (int e = 0; e < NE; e++) {
            float s = 0.f;
#pragma unroll
            for (int w = 0; w < 8; w++) s += red[w][e];
            l[e] = s;
        }
        float m = l[0]; int bi = 0;
#pragma unroll
        for (int e = 1; e < NE; e++) {
            if (l[e] > m) { m = l[e]; bi = e; }  // first-max = jnp.argmax
        }
        float s = 0.f;
#pragma unroll
        for (int e = 0; e < NE; e++) s += expf(l[e] - m);
        g_w[t] = 1.0f / s;
        const int slot = atomicAdd(&g_counts[bi], 1);
        g_tok[bi][slot] = t;
    }
}

// -------- asm helpers --------
static __device__ __forceinline__ uint32_t f2tf32(float f) {
    uint32_t u; asm("cvt.rna.tf32.f32 %0, %1;" : "=r"(u) : "f"(f)); return u;
}
static __device__ __forceinline__ void sts128(uint32_t a, uint32_t x, uint32_t y,
                                              uint32_t z, uint32_t w) {
    asm volatile("st.shared.v4.b32 [%0], {%1,%2,%3,%4};"
                 :: "r"(a), "r"(x), "r"(y), "r"(z), "r"(w));
}
static __device__ __forceinline__ void lds128(uint32_t a, uint32_t* r) {
    asm volatile("ld.shared.v4.b32 {%0,%1,%2,%3}, [%4];"
                 : "=r"(r[0]), "=r"(r[1]), "=r"(r[2]), "=r"(r[3]) : "r"(a));
}
static __device__ __forceinline__ void mma_tf32(float* c, const uint32_t* a, const uint32_t* b) {
    asm volatile(
        "mma.sync.aligned.m16n8k8.row.col.f32.tf32.tf32.f32 "
        "{%0,%1,%2,%3}, {%4,%5,%6,%7}, {%8,%9}, {%0,%1,%2,%3};"
        : "+f"(c[0]), "+f"(c[1]), "+f"(c[2]), "+f"(c[3])
        : "r"(a[0]), "r"(a[1]), "r"(a[2]), "r"(a[3]), "r"(b[0]), "r"(b[1]));
}

// -------- grouped TF32 GEMM, fragment-ordered smem, 64x64 warp tiles --------
// A word (16B) @ tile(mrow*4+kseg), word(rlow*4+kc) = {(r,k),(r+8,k),(r,k+4),(r+8,k+4)}
// B word (16B) @ tile(kseg*16+npair), word(qr*4+qc) = {(k,n),(k+4,n),(k,n+8),(k+4,n+8)}
template <bool F1>
__global__ __launch_bounds__(256, 1)
void moe_mma(const float* __restrict__ Asrc,
             const float* __restrict__ W,
             float* __restrict__ Out) {
    constexpr int KD = F1 ? NDM : NF;
    constexpr int ND = F1 ? NF : NDM;
    constexpr int NK = KD / BK;

    const int e   = blockIdx.z;
    const int cnt = g_counts[e];
    const int m0  = blockIdx.y * BM;
    if (m0 >= cnt) return;
    const int n0  = blockIdx.x * BN;

    extern __shared__ float smem[];
    int* toks = (int*)((char*)smem + 2 * STAGE_B);
    const uint32_t sbase = (uint32_t)__cvta_generic_to_shared(smem);

    const int tid  = threadIdx.x;
    const int wid  = tid >> 5;
    const int lane = tid & 31;

    if (tid < BM) {
        const int m = m0 + tid;
        toks[tid] = (m < cnt) ? g_tok[e][m] : -1;
    }
    __syncthreads();

    const float* A = F1 ? Asrc : (const float*)g_h;

    // ---- A loader: thread -> rows (r, r+8), k-range kseg*8..+7
    const int a_ks   = tid & 3;
    const int a_rp   = tid >> 2;
    const int a_rlow = a_rp & 7;
    const int a_mrow = a_rp >> 3;          // 0..7
    const int ar0 = a_mrow * 16 + a_rlow;
    const int atok0 = toks[ar0];
    const int atok1 = toks[ar0 + 8];
    const float* ap0 = A + (atok0 >= 0 ? (size_t)atok0 * KD : 0) + a_ks * 8;
    const float* ap1 = A + (atok1 >= 0 ? (size_t)atok1 * KD : 0) + a_ks * 8;
    const uint32_t a_sts = sbase +
        (uint32_t)(((a_mrow * 4 + a_ks) * A_TILE_W + a_rlow * 4) * 16);

    // ---- B loader: thread -> rows (klo, klo+4), two npair groups (np0, np0+8)
    const int b_kc  = tid & 3;
    const int b_npl = (tid >> 2) & 3;
    const int b_ns  = (tid >> 4) & 1;
    const int b_ksg = (tid >> 5) & 3;
    const int b_nph = (tid >> 7) & 1;
    const int b_np0 = b_nph * 4 + b_npl;   // 0..7 ; second group = +8
    const int b_nb  = b_np0 * 16 + b_ns * 4;
    const int b_klo = b_ksg * 8 + b_kc;
    const float* bp = W + (size_t)e * KD * ND + (size_t)b_klo * ND + (n0 + b_nb);
    const uint32_t b_sts = sbase + A_STAGE_B +
        (uint32_t)(((b_ksg * 16 + b_np0) * B_TILE_W + b_ns * 16 + b_kc) * 16);
    const uint32_t b_sts2 = b_sts + (uint32_t)(8 * B_TILE_W * 16);

    // ---- consumer bases: warp tile 64x64; wm = M half, wn = N quarter
    const int wm = wid & 1;
    const int wn = wid >> 1;
    const uint32_t aLds0 = sbase + (uint32_t)(wm * 16 * A_TILE_W * 16) + lane * 16;
    const uint32_t bLds0 = sbase + A_STAGE_B + (uint32_t)(wn * 4 * B_TILE_W * 16) + lane * 16;

    float4 fa0, fa1, fb0, fb1;             // A prefetch (2 rows x 8k)
    float4 g0, g1, g2, g3, g4, g5, g6, g7; // B prefetch (2 k-rows x 2 n-quads x 2 groups)

#define LOAD(T)                                                            \
    {                                                                      \
        const float* _a0 = ap0 + (size_t)(T) * BK;                         \
        const float* _a1 = ap1 + (size_t)(T) * BK;                         \
        fa0 = *(const float4*)_a0; fa1 = *(const float4*)(_a0 + 4);        \
        fb0 = *(const float4*)_a1; fb1 = *(const float4*)(_a1 + 4);        \
        const float* _b = bp + (size_t)(T) * BK * ND;                      \
        g0 = *(const float4*)_b;                                           \
        g1 = *(const float4*)(_b + 8);                                     \
        g2 = *(const float4*)(_b + 4 * (size_t)ND);                        \
        g3 = *(const float4*)(_b + 4 * (size_t)ND + 8);                    \
        g4 = *(const float4*)(_b + 128);                                   \
        g5 = *(const float4*)(_b + 136);                                   \
        g6 = *(const float4*)(_b + 4 * (size_t)ND + 128);                  \
        g7 = *(const float4*)(_b + 4 * (size_t)ND + 136);                  \
    }

#define STORE(OFF)                                                         \
    {                                                                      \
        const uint32_t _as = a_sts + (OFF);                                \
        sts128(_as,      f2tf32(fa0.x), f2tf32(fb0.x), f2tf32(fa1.x), f2tf32(fb1.x)); \
        sts128(_as + 16, f2tf32(fa0.y), f2tf32(fb0.y), f2tf32(fa1.y), f2tf32(fb1.y)); \
        sts128(_as + 32, f2tf32(fa0.z), f2tf32(fb0.z), f2tf32(fa1.z), f2tf32(fb1.z)); \
        sts128(_as + 48, f2tf32(fa0.w), f2tf32(fb0.w), f2tf32(fa1.w), f2tf32(fb1.w)); \
        const uint32_t _bs = b_sts + (OFF);                                \
        sts128(_bs,       f2tf32(g0.x), f2tf32(g2.x), f2tf32(g1.x), f2tf32(g3.x)); \
        sts128(_bs + 64,  f2tf32(g0.y), f2tf32(g2.y), f2tf32(g1.y), f2tf32(g3.y)); \
        sts128(_bs + 128, f2tf32(g0.z), f2tf32(g2.z), f2tf32(g1.z), f2tf32(g3.z)); \
        sts128(_bs + 192, f2tf32(g0.w), f2tf32(g2.w), f2tf32(g1.w), f2tf32(g3.w)); \
        const uint32_t _b2 = b_sts2 + (OFF);                               \
        sts128(_b2,       f2tf32(g4.x), f2tf32(g6.x), f2tf32(g5.x), f2tf32(g7.x)); \
        sts128(_b2 + 64,  f2tf32(g4.y), f2tf32(g6.y), f2tf32(g5.y), f2tf32(g7.y)); \
        sts128(_b2 + 128, f2tf32(g4.z), f2tf32(g6.z), f2tf32(g5.z), f2tf32(g7.z)); \
        sts128(_b2 + 192, f2tf32(g4.w), f2tf32(g6.w), f2tf32(g5.w), f2tf32(g7.w)); \
    }

    float acc[4][4][2][4];
#pragma unroll
    for (int i = 0; i < 4; i++)
#pragma unroll
        for (int p = 0; p < 4; p++)
#pragma unroll
            for (int s = 0; s < 2; s++)
#pragma unroll
                for (int q = 0; q < 4; q++) acc[i][p][s][q] = 0.f;

#define MMASTEP(OFF)                                                        \
    {                                                                       \
        _Pragma("unroll") for (int ks = 0; ks < 4; ks++) {                  \
            uint32_t af[4][4];                                              \
            _Pragma("unroll") for (int i = 0; i < 4; i++)                   \
                lds128(aLds0 + (OFF) + (i * 4 + ks) * (A_TILE_W * 16), af[i]); \
            _Pragma("unroll") for (int p = 0; p < 4; p++) {                 \
                uint32_t bf[4];                                             \
                lds128(bLds0 + (OFF) + (ks * 16 + p) * (B_TILE_W * 16), bf);\
                _Pragma("unroll") for (int i = 0; i < 4; i++) {             \
                    mma_tf32(acc[i][p][0], af[i], bf);                      \
                    mma_tf32(acc[i][p][1], af[i], bf + 2);                  \
                }                                                           \
            }                                                               \
        }                                                                   \
    }

    LOAD(0)
    STORE(0)
    __syncthreads();

#pragma unroll 1
    for (int t = 0; t < NK; t++) {
        const bool more = (t + 1 < NK);
        if (more) LOAD(t + 1)
        MMASTEP((uint32_t)((t & 1) * STAGE_B))
        __syncthreads();
        if (more) {
            STORE((uint32_t)(((t + 1) & 1) * STAGE_B))
            __syncthreads();
        }
    }

    // ---- epilogue
    const int qr = lane >> 2;
    const int qc = lane & 3;
#pragma unroll
    for (int i = 0; i < 4; i++) {
        const int r0 = wm * 64 + i * 16 + qr;
        const int tok0 = toks[r0];
        const int tok1 = toks[r0 + 8];
#pragma unroll
        for (int p = 0; p < 4; p++)
#pragma unroll
            for (int sub = 0; sub < 2; sub++) {
                const int col = n0 + wn * 64 + p * 16 + sub * 8 + qc * 2;
                const float* c = acc[i][p][sub];
                if (F1) {
                    if (tok0 >= 0) {
                        float2 v = make_float2(gelu_exact(c[0]), gelu_exact(c[1]));
                        *(float2*)(g_h + (size_t)tok0 * NF + col) = v;
                    }
                    if (tok1 >= 0) {
                        float2 v = make_float2(gelu_exact(c[2]), gelu_exact(c[3]));
                        *(float2*)(g_h + (size_t)tok1 * NF + col) = v;
                    }
                } else {
                    if (tok0 >= 0) {
                        const float w0 = g_w[tok0];
                        float2 v = make_float2(c[0] * w0, c[1] * w0);
                        *(float2*)(Out + (size_t)tok0 * NDM + col) = v;
                    }
                    if (tok1 >= 0) {
                        const float w1 = g_w[tok1];
                        float2 v = make_float2(c[2] * w1, c[3] * w1);
                        *(float2*)(Out + (size_t)tok1 * NDM + col) = v;
                    }
                }
            }
    }
#undef LOAD
#undef STORE
#undef MMASTEP
}

extern "C" void kernel_launch(void* const* d_in, const int* in_sizes, int n_in,
                              void* d_out, int out_size) {
    (void)in_sizes; (void)n_in; (void)out_size;
    const float* x  = (const float*)d_in[0];
    const float* Wr = (const float*)d_in[1];
    const float* W1 = (const float*)d_in[2];
    const float* W2 = (const float*)d_in[3];
    float* out = (float*)d_out;

    cudaFuncSetAttribute(moe_mma<true>,  cudaFuncAttributeMaxDynamicSharedMemorySize, SMEM_BYTES);
    cudaFuncSetAttribute(moe_mma<false>, cudaFuncAttributeMaxDynamicSharedMemorySize, SMEM_BYTES);

    reset_kernel<<<1, 32>>>();
    router_kernel<<<NT, 256>>>(x, Wr);

    dim3 g1(NF / BN, NT / BM, NE);    // (32, 32, 8)
    moe_mma<true><<<g1, 256, SMEM_BYTES>>>(x, W1, out);

    dim3 g2(NDM / BN, NT / BM, NE);   // (8, 32, 8)
    moe_mma<false><<<g2, 256, SMEM_BYTES>>>(x, W2, out);
}